// round 1
// baseline (speedup 1.0000x reference)
#include <cuda_runtime.h>
#include <math.h>

// ---------------- problem constants ----------------
#define Bsz 64
#define Hd  256
#define Dd  768
#define NRn 100000
#define ERn 400000
#define NCn 100000
#define ECn 300000
#define Gn  512

// ---------------- device scratch (allocation-free rule: __device__ globals) ----------------
__device__ float g_XWr[(size_t)NRn * Hd];   // repost: X@Wf, later reused for P2
__device__ float g_P1r[(size_t)NRn * Hd];   // repost: propagated conv1 (pre-relu)
__device__ float g_XWc[(size_t)NCn * Hd];
__device__ float g_P1c[(size_t)NCn * Hd];
__device__ float g_dinv_r[NRn];
__device__ float g_dinv_c[NCn];
__device__ float g_Wf_r[Dd * Hd];           // W_text @ Wr1
__device__ float g_Wf_c[Dd * Hd];           // W_text @ Wc1
__device__ float g_pooled_r[Bsz * Hd];
__device__ float g_pooledG[Gn * Hd];
__device__ float g_graphs[Gn * Hd];
__device__ float g_poolC[Bsz * Hd];
__device__ float g_reps[Bsz * 5 * Hd];
__device__ float g_hmid[Bsz * Hd];

// ---------------- small utility kernels ----------------
__global__ void fillf_kernel(float* p, int n, float v) {
    int i = blockIdx.x * blockDim.x + threadIdx.x;
    if (i < n) p[i] = v;
}

__global__ void deg_add_kernel(const int* __restrict__ dst, float* __restrict__ deg, int E) {
    int e = blockIdx.x * blockDim.x + threadIdx.x;
    if (e < E) atomicAdd(&deg[dst[e]], 1.0f);
}

__global__ void inv_sqrt_kernel(float* p, int n) {
    int i = blockIdx.x * blockDim.x + threadIdx.x;
    if (i < n) p[i] = 1.0f / sqrtf(p[i]);
}

// self-loop term (initializes out): out[n] = act(in[n]) * dinv[n]^2
__global__ void prop_self_kernel(const float* __restrict__ in, float* __restrict__ out,
                                 const float* __restrict__ dinv, int doRelu) {
    int n = blockIdx.x;
    int j = threadIdx.x;            // Hd threads
    float di = dinv[n];
    float v = in[(size_t)n * Hd + j];
    if (doRelu) v = fmaxf(v, 0.0f);
    out[(size_t)n * Hd + j] = v * di * di;
}

// edge scatter: out[dst] += act(in[src]) * dinv[src]*dinv[dst]
__global__ void prop_edges_kernel(const float* __restrict__ in, float* __restrict__ out,
                                  const int* __restrict__ src, const int* __restrict__ dst,
                                  const float* __restrict__ dinv, int doRelu) {
    int e = blockIdx.x;
    int j = threadIdx.x;            // Hd threads
    int s = src[e];
    int d = dst[e];
    float coef = dinv[s] * dinv[d];
    float v = in[(size_t)s * Hd + j];
    if (doRelu) v = fmaxf(v, 0.0f);
    atomicAdd(&out[(size_t)d * Hd + j], v * coef);
}

__device__ __forceinline__ int lower_bound_dev(const int* a, int n, int v) {
    int lo = 0, hi = n;
    while (lo < hi) { int mid = (lo + hi) >> 1; if (a[mid] < v) lo = mid + 1; else hi = mid; }
    return lo;
}

// segmented (sorted seg array) partial sums: atomicAdd into acc[b*Hd + j]
__global__ void pool_partial_kernel(const float* __restrict__ x, const int* __restrict__ seg,
                                    int n, float* __restrict__ acc, int chunks) {
    int b = blockIdx.x;
    int chunk = blockIdx.y;
    int start = lower_bound_dev(seg, n, b);
    int end   = lower_bound_dev(seg, n, b + 1);
    int len = end - start;
    if (len <= 0) return;
    int per = (len + chunks - 1) / chunks;
    int s0 = start + chunk * per;
    int s1 = s0 + per; if (s1 > end) s1 = end;
    if (s0 >= s1) return;
    int j = threadIdx.x;
    float a = 0.0f;
    for (int r = s0; r < s1; r++) a += x[(size_t)r * Hd + j];
    atomicAdd(&acc[b * Hd + j], a);
}

// divide by count, write (optionally strided) destination
__global__ void pool_div_kernel(const float* __restrict__ acc, const int* __restrict__ seg,
                                int n, float* __restrict__ dst, int ld) {
    int b = blockIdx.x;
    int j = threadIdx.x;
    int cnt = lower_bound_dev(seg, n, b + 1) - lower_bound_dev(seg, n, b);
    float c = fmaxf((float)cnt, 1.0f);
    dst[(size_t)b * ld + j] = acc[b * Hd + j] / c;
}

// ---------------- big GEMM: C[M,N] = A[M,K] @ B[K,N], fp32, N multiple of 128, K multiple of 16 ----------------
__global__ __launch_bounds__(256) void sgemm128_kernel(const float* __restrict__ A, int lda,
                                                       const float* __restrict__ Bm,
                                                       float* __restrict__ C,
                                                       int M, int N, int K) {
    const int BM = 128, BN = 128, BK = 16, TM = 8, TN = 8;
    __shared__ float As[BK][BM];
    __shared__ float Bs[BK][BN];
    const int tid = threadIdx.x;
    const int bRow = blockIdx.y * BM;
    const int bCol = blockIdx.x * BN;
    const int tx = tid % 16;
    const int ty = tid / 16;

    float acc[TM][TN];
#pragma unroll
    for (int i = 0; i < TM; i++)
#pragma unroll
        for (int j = 0; j < TN; j++) acc[i][j] = 0.0f;

    for (int k0 = 0; k0 < K; k0 += BK) {
        // load A tile: 128x16 = 512 float4, 2 per thread
#pragma unroll
        for (int l = 0; l < 2; l++) {
            int i = tid + l * 256;
            int r = i >> 2;
            int c4 = (i & 3) << 2;
            int grow = bRow + r;
            float4 v = make_float4(0.f, 0.f, 0.f, 0.f);
            if (grow < M) v = *reinterpret_cast<const float4*>(&A[(size_t)grow * lda + k0 + c4]);
            As[c4 + 0][r] = v.x; As[c4 + 1][r] = v.y; As[c4 + 2][r] = v.z; As[c4 + 3][r] = v.w;
        }
        // load B tile: 16x128 = 512 float4, 2 per thread
#pragma unroll
        for (int l = 0; l < 2; l++) {
            int i = tid + l * 256;
            int r = i >> 5;
            int c = (i & 31) << 2;
            float4 v = *reinterpret_cast<const float4*>(&Bm[(size_t)(k0 + r) * N + bCol + c]);
            *reinterpret_cast<float4*>(&Bs[r][c]) = v;
        }
        __syncthreads();

        float ar[TM], br[TN];
#pragma unroll
        for (int kk = 0; kk < BK; kk++) {
#pragma unroll
            for (int i = 0; i < TM; i++) ar[i] = As[kk][ty * TM + i];
#pragma unroll
            for (int j = 0; j < TN; j++) br[j] = Bs[kk][tx * TN + j];
#pragma unroll
            for (int i = 0; i < TM; i++)
#pragma unroll
                for (int j = 0; j < TN; j++) acc[i][j] += ar[i] * br[j];
        }
        __syncthreads();
    }

#pragma unroll
    for (int i = 0; i < TM; i++) {
        int grow = bRow + ty * TM + i;
        if (grow >= M) continue;
#pragma unroll
        for (int j = 0; j < TN; j += 4) {
            float4 v = make_float4(acc[i][j], acc[i][j + 1], acc[i][j + 2], acc[i][j + 3]);
            *reinterpret_cast<float4*>(&C[(size_t)grow * N + bCol + tx * TN + j]) = v;
        }
    }
}

// ---------------- small GEMM: C = act(A[M,K] @ B[K,N] + bias), N multiple of 64, K multiple of 16 ----------------
__global__ __launch_bounds__(256) void sgemm64_kernel(const float* __restrict__ A, int lda,
                                                      const float* __restrict__ Bm,
                                                      const float* __restrict__ bias,
                                                      float* __restrict__ C, int ldc,
                                                      int M, int N, int K, int doRelu) {
    const int BM = 64, BN = 64, BK = 16, TM = 4, TN = 4;
    __shared__ float As[BK][BM];
    __shared__ float Bs[BK][BN];
    const int tid = threadIdx.x;
    const int bRow = blockIdx.y * BM;
    const int bCol = blockIdx.x * BN;
    const int tx = tid % 16;
    const int ty = tid / 16;

    float acc[TM][TN];
#pragma unroll
    for (int i = 0; i < TM; i++)
#pragma unroll
        for (int j = 0; j < TN; j++) acc[i][j] = 0.0f;

    for (int k0 = 0; k0 < K; k0 += BK) {
        {   // A tile: 64x16 = 256 float4, 1 per thread
            int i = tid;
            int r = i >> 2;
            int c4 = (i & 3) << 2;
            int grow = bRow + r;
            float4 v = make_float4(0.f, 0.f, 0.f, 0.f);
            if (grow < M) v = *reinterpret_cast<const float4*>(&A[(size_t)grow * lda + k0 + c4]);
            As[c4 + 0][r] = v.x; As[c4 + 1][r] = v.y; As[c4 + 2][r] = v.z; As[c4 + 3][r] = v.w;
        }
        {   // B tile: 16x64 = 256 float4, 1 per thread
            int i = tid;
            int r = i >> 4;
            int c = (i & 15) << 2;
            float4 v = *reinterpret_cast<const float4*>(&Bm[(size_t)(k0 + r) * N + bCol + c]);
            *reinterpret_cast<float4*>(&Bs[r][c]) = v;
        }
        __syncthreads();

        float ar[TM], br[TN];
#pragma unroll
        for (int kk = 0; kk < BK; kk++) {
#pragma unroll
            for (int i = 0; i < TM; i++) ar[i] = As[kk][ty * TM + i];
#pragma unroll
            for (int j = 0; j < TN; j++) br[j] = Bs[kk][tx * TN + j];
#pragma unroll
            for (int i = 0; i < TM; i++)
#pragma unroll
                for (int j = 0; j < TN; j++) acc[i][j] += ar[i] * br[j];
        }
        __syncthreads();
    }

#pragma unroll
    for (int i = 0; i < TM; i++) {
        int grow = bRow + ty * TM + i;
        if (grow >= M) continue;
#pragma unroll
        for (int j = 0; j < TN; j++) {
            int gcol = bCol + tx * TN + j;
            float v = acc[i][j];
            if (bias) v += bias[gcol];
            if (doRelu) v = fmaxf(v, 0.0f);
            C[(size_t)grow * ldc + gcol] = v;
        }
    }
}

// ---------------- head: preds = h@W2 + b2, log-softmax, NLL loss ----------------
__global__ void head_kernel(const float* __restrict__ h, const float* __restrict__ W2,
                            const float* __restrict__ b2, const int* __restrict__ label,
                            float* __restrict__ out, int out_size) {
    __shared__ float preds[Bsz][2];
    int tid = threadIdx.x;  // 128 threads
    if (tid < Bsz * 2) {
        int r = tid >> 1, c = tid & 1;
        float s = b2[c];
        for (int k = 0; k < Hd; k++) s += h[r * Hd + k] * W2[k * 2 + c];
        preds[r][c] = s;
    }
    __syncthreads();
    if (tid < Bsz * 2 && tid < out_size) out[tid] = preds[tid >> 1][tid & 1];
    if (tid == 0 && out_size >= Bsz * 2 + 1) {
        float loss = 0.0f;
        for (int r = 0; r < Bsz; r++) {
            float a = preds[r][0], b = preds[r][1];
            float m = fmaxf(a, b);
            float lse = m + logf(expf(a - m) + expf(b - m));
            int y = label[r];
            loss += lse - (y ? b : a);
        }
        out[Bsz * 2] = loss / (float)Bsz;
    }
}

// ---------------- launch ----------------
extern "C" void kernel_launch(void* const* d_in, const int* in_sizes, int n_in,
                              void* d_out, int out_size) {
    const float* content  = (const float*)d_in[0];
    const float* video    = (const float*)d_in[1];
    const float* image    = (const float*)d_in[2];
    const float* repost_x = (const float*)d_in[3];
    const float* comment_x= (const float*)d_in[4];
    const float* W_text   = (const float*)d_in[5];
    const float* W_video  = (const float*)d_in[6];
    const float* W_image  = (const float*)d_in[7];
    const float* Wr1      = (const float*)d_in[8];
    const float* Wr2      = (const float*)d_in[9];
    const float* Wc1      = (const float*)d_in[10];
    const float* Wc2      = (const float*)d_in[11];
    const float* W1       = (const float*)d_in[12];
    const float* b1       = (const float*)d_in[13];
    const float* W2       = (const float*)d_in[14];
    const float* b2       = (const float*)d_in[15];
    const int* rei        = (const int*)d_in[16];   // [2, ER]: src then dst
    const int* rbatch     = (const int*)d_in[17];
    const int* cei        = (const int*)d_in[18];   // [2, EC]
    const int* cbatch     = (const int*)d_in[19];
    const int* cgb        = (const int*)d_in[20];
    const int* label      = (const int*)d_in[21];
    float* out            = (float*)d_out;

    float *pXWr, *pP1r, *pXWc, *pP1c, *pDr, *pDc, *pWfr, *pWfc;
    float *pPoolR, *pPoolG, *pGraphs, *pPoolC, *pReps, *pHmid;
    cudaGetSymbolAddress((void**)&pXWr, g_XWr);
    cudaGetSymbolAddress((void**)&pP1r, g_P1r);
    cudaGetSymbolAddress((void**)&pXWc, g_XWc);
    cudaGetSymbolAddress((void**)&pP1c, g_P1c);
    cudaGetSymbolAddress((void**)&pDr, g_dinv_r);
    cudaGetSymbolAddress((void**)&pDc, g_dinv_c);
    cudaGetSymbolAddress((void**)&pWfr, g_Wf_r);
    cudaGetSymbolAddress((void**)&pWfc, g_Wf_c);
    cudaGetSymbolAddress((void**)&pPoolR, g_pooled_r);
    cudaGetSymbolAddress((void**)&pPoolG, g_pooledG);
    cudaGetSymbolAddress((void**)&pGraphs, g_graphs);
    cudaGetSymbolAddress((void**)&pPoolC, g_poolC);
    cudaGetSymbolAddress((void**)&pReps, g_reps);
    cudaGetSymbolAddress((void**)&pHmid, g_hmid);

    const int* r_src = rei;            const int* r_dst = rei + ERn;
    const int* c_src = cei;            const int* c_dst = cei + ECn;

    // ---- degrees / dinv (re-done every call; deterministic across replays) ----
    fillf_kernel<<<(NRn + 255) / 256, 256>>>(pDr, NRn, 1.0f);
    deg_add_kernel<<<(ERn + 255) / 256, 256>>>(r_dst, pDr, ERn);
    inv_sqrt_kernel<<<(NRn + 255) / 256, 256>>>(pDr, NRn);
    fillf_kernel<<<(NCn + 255) / 256, 256>>>(pDc, NCn, 1.0f);
    deg_add_kernel<<<(ECn + 255) / 256, 256>>>(c_dst, pDc, ECn);
    inv_sqrt_kernel<<<(NCn + 255) / 256, 256>>>(pDc, NCn);

    // ---- fused first-layer weights: Wf = W_text @ W*1   [768,256] ----
    sgemm64_kernel<<<dim3(Hd / 64, Dd / 64), 256>>>(W_text, Hd, Wr1, nullptr, pWfr, Hd, Dd, Hd, Hd, 0);
    sgemm64_kernel<<<dim3(Hd / 64, Dd / 64), 256>>>(W_text, Hd, Wc1, nullptr, pWfc, Hd, Dd, Hd, Hd, 0);

    // ---- big GEMMs: XW = X @ Wf   [N,256] ----
    sgemm128_kernel<<<dim3(Hd / 128, (NRn + 127) / 128), 256>>>(repost_x, Dd, pWfr, pXWr, NRn, Hd, Dd);
    sgemm128_kernel<<<dim3(Hd / 128, (NCn + 127) / 128), 256>>>(comment_x, Dd, pWfc, pXWc, NCn, Hd, Dd);

    // ---- repost branch: P1 = P(XW); P2 = P(relu(P1)) -> pooled ----
    prop_self_kernel<<<NRn, Hd>>>(pXWr, pP1r, pDr, 0);
    prop_edges_kernel<<<ERn, Hd>>>(pXWr, pP1r, r_src, r_dst, pDr, 0);
    prop_self_kernel<<<NRn, Hd>>>(pP1r, pXWr, pDr, 1);
    prop_edges_kernel<<<ERn, Hd>>>(pP1r, pXWr, r_src, r_dst, pDr, 1);
    cudaMemsetAsync(pPoolR, 0, (size_t)Bsz * Hd * sizeof(float));
    pool_partial_kernel<<<dim3(Bsz, 16), Hd>>>(pXWr, rbatch, NRn, pPoolR, 16);
    pool_div_kernel<<<Bsz, Hd>>>(pPoolR, rbatch, NRn, pPoolR, Hd);

    // ---- comment branch ----
    prop_self_kernel<<<NCn, Hd>>>(pXWc, pP1c, pDc, 0);
    prop_edges_kernel<<<ECn, Hd>>>(pXWc, pP1c, c_src, c_dst, pDc, 0);
    prop_self_kernel<<<NCn, Hd>>>(pP1c, pXWc, pDc, 1);
    prop_edges_kernel<<<ECn, Hd>>>(pP1c, pXWc, c_src, c_dst, pDc, 1);
    cudaMemsetAsync(pPoolG, 0, (size_t)Gn * Hd * sizeof(float));
    pool_partial_kernel<<<dim3(Gn, 4), Hd>>>(pXWc, cbatch, NCn, pPoolG, 4);
    pool_div_kernel<<<Gn, Hd>>>(pPoolG, cbatch, NCn, pPoolG, Hd);

    // graphs_reps = pooledG @ Wc2   [512,256]
    sgemm64_kernel<<<dim3(Hd / 64, Gn / 64), 256>>>(pPoolG, Hd, Wc2, nullptr, pGraphs, Hd, Gn, Hd, Hd, 0);
    // comment_reps = mean over graph segments -> reps[:, 512:768]
    cudaMemsetAsync(pPoolC, 0, (size_t)Bsz * Hd * sizeof(float));
    pool_partial_kernel<<<dim3(Bsz, 2), Hd>>>(pGraphs, cgb, Gn, pPoolC, 2);
    pool_div_kernel<<<Bsz, Hd>>>(pPoolC, cgb, Gn, pReps + 2 * Hd, 5 * Hd);

    // ---- assemble reps [64, 1280] ----
    sgemm64_kernel<<<dim3(Hd / 64, 1), 256>>>(content, Dd, W_text, nullptr, pReps + 0 * Hd, 5 * Hd, Bsz, Hd, Dd, 0);
    sgemm64_kernel<<<dim3(Hd / 64, 1), 256>>>(pPoolR, Hd, Wr2, nullptr, pReps + 1 * Hd, 5 * Hd, Bsz, Hd, Hd, 0);
    sgemm64_kernel<<<dim3(Hd / 64, 1), 256>>>(video, Dd, W_video, nullptr, pReps + 3 * Hd, 5 * Hd, Bsz, Hd, Dd, 0);
    sgemm64_kernel<<<dim3(Hd / 64, 1), 256>>>(image, Dd, W_image, nullptr, pReps + 4 * Hd, 5 * Hd, Bsz, Hd, Dd, 0);

    // ---- MLP head ----
    sgemm64_kernel<<<dim3(Hd / 64, 1), 256>>>(pReps, 5 * Hd, W1, b1, pHmid, Hd, Bsz, Hd, 5 * Hd, 1);
    head_kernel<<<1, 128>>>(pHmid, W2, b2, label, out, out_size);
}

// round 2
// speedup vs baseline: 1.4011x; 1.4011x over previous
#include <cuda_runtime.h>
#include <cuda_bf16.h>
#include <math.h>
#include <stdint.h>

// ---------------- problem constants ----------------
#define Bsz 64
#define Hd  256
#define Dd  768
#define NRn 100000
#define ERn 400000
#define NCn 100000
#define ECn 300000
#define Gn  512

// ---------------- device scratch ----------------
__device__ float g_XWr[(size_t)NRn * Hd];
__device__ float g_P1r[(size_t)NRn * Hd];
__device__ float g_XWc[(size_t)NCn * Hd];
__device__ float g_P1c[(size_t)NCn * Hd];
__device__ float g_dinv_r[NRn];
__device__ float g_dinv_c[NCn];
__device__ float g_Wf_r[Dd * Hd];
__device__ float g_Wf_c[Dd * Hd];
__device__ __nv_bfloat16 g_WfT_hi[Hd * Dd];   // [256][768] transposed split weights
__device__ __nv_bfloat16 g_WfT_lo[Hd * Dd];
__device__ float g_pooled_r[Bsz * Hd];
__device__ float g_pooledG[Gn * Hd];
__device__ float g_graphs[Gn * Hd];
__device__ float g_poolC[Bsz * Hd];
__device__ float g_reps[Bsz * 5 * Hd];
__device__ float g_hmid[Bsz * Hd];

// ---------------- small utility kernels ----------------
__global__ void fillf_kernel(float* p, int n, float v) {
    int i = blockIdx.x * blockDim.x + threadIdx.x;
    if (i < n) p[i] = v;
}

__global__ void deg_add_kernel(const int* __restrict__ dst, float* __restrict__ deg, int E) {
    int e = blockIdx.x * blockDim.x + threadIdx.x;
    if (e < E) atomicAdd(&deg[dst[e]], 1.0f);
}

__global__ void inv_sqrt_kernel(float* p, int n) {
    int i = blockIdx.x * blockDim.x + threadIdx.x;
    if (i < n) p[i] = 1.0f / sqrtf(p[i]);
}

__global__ void prop_self_kernel(const float* __restrict__ in, float* __restrict__ out,
                                 const float* __restrict__ dinv, int doRelu) {
    int n = blockIdx.x;
    int j = threadIdx.x;
    float di = dinv[n];
    float v = in[(size_t)n * Hd + j];
    if (doRelu) v = fmaxf(v, 0.0f);
    out[(size_t)n * Hd + j] = v * di * di;
}

__global__ void prop_edges_kernel(const float* __restrict__ in, float* __restrict__ out,
                                  const int* __restrict__ src, const int* __restrict__ dst,
                                  const float* __restrict__ dinv, int doRelu) {
    int e = blockIdx.x;
    int j = threadIdx.x;
    int s = src[e];
    int d = dst[e];
    float coef = dinv[s] * dinv[d];
    float v = in[(size_t)s * Hd + j];
    if (doRelu) v = fmaxf(v, 0.0f);
    atomicAdd(&out[(size_t)d * Hd + j], v * coef);
}

__device__ __forceinline__ int lower_bound_dev(const int* a, int n, int v) {
    int lo = 0, hi = n;
    while (lo < hi) { int mid = (lo + hi) >> 1; if (a[mid] < v) lo = mid + 1; else hi = mid; }
    return lo;
}

__global__ void pool_partial_kernel(const float* __restrict__ x, const int* __restrict__ seg,
                                    int n, float* __restrict__ acc, int chunks) {
    int b = blockIdx.x;
    int chunk = blockIdx.y;
    int start = lower_bound_dev(seg, n, b);
    int end   = lower_bound_dev(seg, n, b + 1);
    int len = end - start;
    if (len <= 0) return;
    int per = (len + chunks - 1) / chunks;
    int s0 = start + chunk * per;
    int s1 = s0 + per; if (s1 > end) s1 = end;
    if (s0 >= s1) return;
    int j = threadIdx.x;
    float a = 0.0f;
    for (int r = s0; r < s1; r++) a += x[(size_t)r * Hd + j];
    atomicAdd(&acc[b * Hd + j], a);
}

__global__ void pool_div_kernel(const float* __restrict__ acc, const int* __restrict__ seg,
                                int n, float* __restrict__ dst, int ld) {
    int b = blockIdx.x;
    int j = threadIdx.x;
    int cnt = lower_bound_dev(seg, n, b + 1) - lower_bound_dev(seg, n, b);
    float c = fmaxf((float)cnt, 1.0f);
    dst[(size_t)b * ld + j] = acc[b * Hd + j] / c;
}

// ---------------- transpose + bf16 split of fused weight ----------------
__global__ void convtrans_kernel(const float* __restrict__ W,
                                 __nv_bfloat16* __restrict__ oHi,
                                 __nv_bfloat16* __restrict__ oLo) {
    int i = blockIdx.x * blockDim.x + threadIdx.x;   // over 768*256
    if (i >= Dd * Hd) return;
    int k = i / Hd, n = i % Hd;
    float f = W[i];
    __nv_bfloat16 h = __float2bfloat16(f);
    float r = f - __bfloat162float(h);
    oHi[(size_t)n * Dd + k] = h;
    oLo[(size_t)n * Dd + k] = __float2bfloat16(r);
}

// ---------------- tensor-core GEMM: C[M,256] = A[M,768] @ B, bf16 split (3 products) ----------------
__device__ __forceinline__ void ldsm_x4(uint32_t r[4], const void* p) {
    uint32_t a = (uint32_t)__cvta_generic_to_shared(p);
    asm volatile("ldmatrix.sync.aligned.m8n8.x4.shared.b16 {%0,%1,%2,%3}, [%4];"
                 : "=r"(r[0]), "=r"(r[1]), "=r"(r[2]), "=r"(r[3]) : "r"(a));
}

__device__ __forceinline__ void mma_bf16(float acc[4], uint32_t a0, uint32_t a1,
                                         uint32_t a2, uint32_t a3,
                                         uint32_t b0, uint32_t b1) {
    asm volatile(
        "mma.sync.aligned.m16n8k16.row.col.f32.bf16.bf16.f32 "
        "{%0,%1,%2,%3},{%4,%5,%6,%7},{%8,%9},{%0,%1,%2,%3};"
        : "+f"(acc[0]), "+f"(acc[1]), "+f"(acc[2]), "+f"(acc[3])
        : "r"(a0), "r"(a1), "r"(a2), "r"(a3), "r"(b0), "r"(b1));
}

__global__ __launch_bounds__(256) void gemm_tc_kernel(
    const float* __restrict__ A,                 // [M, 768] fp32 row-major
    const __nv_bfloat16* __restrict__ BtHi,      // [256][768] (N-major)
    const __nv_bfloat16* __restrict__ BtLo,
    float* __restrict__ C, int M)
{
    const int K = Dd;
    const int LDS_STRIDE = 40;                   // 80B row stride -> ldmatrix conflict-free
    __shared__ __nv_bfloat16 AsH[128][LDS_STRIDE];
    __shared__ __nv_bfloat16 AsL[128][LDS_STRIDE];
    __shared__ __nv_bfloat16 BsH[128][LDS_STRIDE];
    __shared__ __nv_bfloat16 BsL[128][LDS_STRIDE];

    int tid = threadIdx.x;
    int warp = tid >> 5, lane = tid & 31;
    int bRow = blockIdx.y * 128, bCol = blockIdx.x * 128;
    int wm = (warp >> 2) * 64;                   // warp m offset (0/64)
    int wn = (warp & 3) * 32;                    // warp n offset (0/32/64/96)

    float acc[4][4][4];
#pragma unroll
    for (int a = 0; a < 4; a++)
#pragma unroll
        for (int b = 0; b < 4; b++)
#pragma unroll
            for (int c = 0; c < 4; c++) acc[a][b][c] = 0.0f;

    // A register prefetch (4 float4/thread covers 128x32 fp32 tile)
    float4 aR[4];
    const float4 z4 = make_float4(0.f, 0.f, 0.f, 0.f);
#define LOAD_A(k0)                                                            \
    {                                                                         \
        _Pragma("unroll")                                                     \
        for (int l = 0; l < 4; l++) {                                         \
            int i = tid + l * 256;                                            \
            int r = i >> 3, c4 = (i & 7) * 4;                                 \
            int gr = bRow + r;                                                \
            aR[l] = (gr < M) ? *(const float4*)&A[(size_t)gr * K + (k0) + c4] \
                             : z4;                                            \
        }                                                                     \
    }

    LOAD_A(0);

    for (int it = 0; it < K / 32; it++) {
        int k0 = it * 32;
        // B tiles (L2-resident) straight to smem
#pragma unroll
        for (int l = 0; l < 2; l++) {
            int i = tid + l * 256;
            int r = i >> 2, c8 = (i & 3) * 8;
            *(float4*)&BsH[r][c8] = *(const float4*)&BtHi[(size_t)(bCol + r) * K + k0 + c8];
            *(float4*)&BsL[r][c8] = *(const float4*)&BtLo[(size_t)(bCol + r) * K + k0 + c8];
        }
        // A: convert prefetched regs to split bf16 and store
#pragma unroll
        for (int l = 0; l < 4; l++) {
            int i = tid + l * 256;
            int r = i >> 3, c4 = (i & 7) * 4;
            float f[4] = {aR[l].x, aR[l].y, aR[l].z, aR[l].w};
            __nv_bfloat16 h[4], lo[4];
#pragma unroll
            for (int j = 0; j < 4; j++) {
                h[j] = __float2bfloat16(f[j]);
                lo[j] = __float2bfloat16(f[j] - __bfloat162float(h[j]));
            }
            *(__nv_bfloat162*)&AsH[r][c4]     = __nv_bfloat162(h[0], h[1]);
            *(__nv_bfloat162*)&AsH[r][c4 + 2] = __nv_bfloat162(h[2], h[3]);
            *(__nv_bfloat162*)&AsL[r][c4]     = __nv_bfloat162(lo[0], lo[1]);
            *(__nv_bfloat162*)&AsL[r][c4 + 2] = __nv_bfloat162(lo[2], lo[3]);
        }
        __syncthreads();

        if (it < K / 32 - 1) LOAD_A(k0 + 32);

        int mt = lane >> 3, ri = lane & 7;
#pragma unroll
        for (int ks = 0; ks < 2; ks++) {
            int colOff = ks * 16 + (mt >> 1) * 8;
            uint32_t aH[4][4], aL[4][4], bH[2][4], bL[2][4];
#pragma unroll
            for (int mi = 0; mi < 4; mi++) {
                int row = wm + mi * 16 + (mt & 1) * 8 + ri;
                ldsm_x4(aH[mi], &AsH[row][colOff]);
                ldsm_x4(aL[mi], &AsL[row][colOff]);
            }
#pragma unroll
            for (int bj = 0; bj < 2; bj++) {
                int row = wn + bj * 16 + (mt & 1) * 8 + ri;
                ldsm_x4(bH[bj], &BsH[row][colOff]);
                ldsm_x4(bL[bj], &BsL[row][colOff]);
            }
#pragma unroll
            for (int mi = 0; mi < 4; mi++)
#pragma unroll
                for (int nj = 0; nj < 4; nj++) {
                    int bj = nj >> 1, s = nj & 1;
                    mma_bf16(acc[mi][nj], aH[mi][0], aH[mi][1], aH[mi][2], aH[mi][3],
                             bH[bj][s], bH[bj][s + 2]);
                    mma_bf16(acc[mi][nj], aH[mi][0], aH[mi][1], aH[mi][2], aH[mi][3],
                             bL[bj][s], bL[bj][s + 2]);
                    mma_bf16(acc[mi][nj], aL[mi][0], aL[mi][1], aL[mi][2], aL[mi][3],
                             bH[bj][s], bH[bj][s + 2]);
                }
        }
        __syncthreads();
    }

    // epilogue
    int g = lane >> 2, t = lane & 3;
#pragma unroll
    for (int mi = 0; mi < 4; mi++)
#pragma unroll
        for (int nj = 0; nj < 4; nj++) {
            int row = bRow + wm + mi * 16 + g;
            int col = bCol + wn + nj * 8 + t * 2;
            if (row < M)
                *(float2*)&C[(size_t)row * Hd + col] = make_float2(acc[mi][nj][0], acc[mi][nj][1]);
            if (row + 8 < M)
                *(float2*)&C[(size_t)(row + 8) * Hd + col] = make_float2(acc[mi][nj][2], acc[mi][nj][3]);
        }
#undef LOAD_A
}

// ---------------- small fp32 GEMM (unchanged) ----------------
__global__ __launch_bounds__(256) void sgemm64_kernel(const float* __restrict__ A, int lda,
                                                      const float* __restrict__ Bm,
                                                      const float* __restrict__ bias,
                                                      float* __restrict__ C, int ldc,
                                                      int M, int N, int K, int doRelu) {
    const int BM = 64, BN = 64, BK = 16, TM = 4, TN = 4;
    __shared__ float As[BK][BM];
    __shared__ float Bs[BK][BN];
    const int tid = threadIdx.x;
    const int bRow = blockIdx.y * BM;
    const int bCol = blockIdx.x * BN;
    const int tx = tid % 16;
    const int ty = tid / 16;

    float acc[TM][TN];
#pragma unroll
    for (int i = 0; i < TM; i++)
#pragma unroll
        for (int j = 0; j < TN; j++) acc[i][j] = 0.0f;

    for (int k0 = 0; k0 < K; k0 += BK) {
        {
            int i = tid;
            int r = i >> 2;
            int c4 = (i & 3) << 2;
            int grow = bRow + r;
            float4 v = make_float4(0.f, 0.f, 0.f, 0.f);
            if (grow < M) v = *reinterpret_cast<const float4*>(&A[(size_t)grow * lda + k0 + c4]);
            As[c4 + 0][r] = v.x; As[c4 + 1][r] = v.y; As[c4 + 2][r] = v.z; As[c4 + 3][r] = v.w;
        }
        {
            int i = tid;
            int r = i >> 4;
            int c = (i & 15) << 2;
            float4 v = *reinterpret_cast<const float4*>(&Bm[(size_t)(k0 + r) * N + bCol + c]);
            *reinterpret_cast<float4*>(&Bs[r][c]) = v;
        }
        __syncthreads();

        float ar[TM], br[TN];
#pragma unroll
        for (int kk = 0; kk < BK; kk++) {
#pragma unroll
            for (int i = 0; i < TM; i++) ar[i] = As[kk][ty * TM + i];
#pragma unroll
            for (int j = 0; j < TN; j++) br[j] = Bs[kk][tx * TN + j];
#pragma unroll
            for (int i = 0; i < TM; i++)
#pragma unroll
                for (int j = 0; j < TN; j++) acc[i][j] += ar[i] * br[j];
        }
        __syncthreads();
    }

#pragma unroll
    for (int i = 0; i < TM; i++) {
        int grow = bRow + ty * TM + i;
        if (grow >= M) continue;
#pragma unroll
        for (int j = 0; j < TN; j++) {
            int gcol = bCol + tx * TN + j;
            float v = acc[i][j];
            if (bias) v += bias[gcol];
            if (doRelu) v = fmaxf(v, 0.0f);
            C[(size_t)grow * ldc + gcol] = v;
        }
    }
}

// ---------------- head ----------------
__global__ void head_kernel(const float* __restrict__ h, const float* __restrict__ W2,
                            const float* __restrict__ b2, const int* __restrict__ label,
                            float* __restrict__ out, int out_size) {
    __shared__ float preds[Bsz][2];
    int tid = threadIdx.x;
    if (tid < Bsz * 2) {
        int r = tid >> 1, c = tid & 1;
        float s = b2[c];
        for (int k = 0; k < Hd; k++) s += h[r * Hd + k] * W2[k * 2 + c];
        preds[r][c] = s;
    }
    __syncthreads();
    if (tid < Bsz * 2 && tid < out_size) out[tid] = preds[tid >> 1][tid & 1];
    if (tid == 0 && out_size >= Bsz * 2 + 1) {
        float loss = 0.0f;
        for (int r = 0; r < Bsz; r++) {
            float a = preds[r][0], b = preds[r][1];
            float m = fmaxf(a, b);
            float lse = m + logf(expf(a - m) + expf(b - m));
            int y = label[r];
            loss += lse - (y ? b : a);
        }
        out[Bsz * 2] = loss / (float)Bsz;
    }
}

// ---------------- launch ----------------
extern "C" void kernel_launch(void* const* d_in, const int* in_sizes, int n_in,
                              void* d_out, int out_size) {
    const float* content  = (const float*)d_in[0];
    const float* video    = (const float*)d_in[1];
    const float* image    = (const float*)d_in[2];
    const float* repost_x = (const float*)d_in[3];
    const float* comment_x= (const float*)d_in[4];
    const float* W_text   = (const float*)d_in[5];
    const float* W_video  = (const float*)d_in[6];
    const float* W_image  = (const float*)d_in[7];
    const float* Wr1      = (const float*)d_in[8];
    const float* Wr2      = (const float*)d_in[9];
    const float* Wc1      = (const float*)d_in[10];
    const float* Wc2      = (const float*)d_in[11];
    const float* W1       = (const float*)d_in[12];
    const float* b1       = (const float*)d_in[13];
    const float* W2       = (const float*)d_in[14];
    const float* b2       = (const float*)d_in[15];
    const int* rei        = (const int*)d_in[16];
    const int* rbatch     = (const int*)d_in[17];
    const int* cei        = (const int*)d_in[18];
    const int* cbatch     = (const int*)d_in[19];
    const int* cgb        = (const int*)d_in[20];
    const int* label      = (const int*)d_in[21];
    float* out            = (float*)d_out;

    float *pXWr, *pP1r, *pXWc, *pP1c, *pDr, *pDc, *pWfr, *pWfc;
    float *pPoolR, *pPoolG, *pGraphs, *pPoolC, *pReps, *pHmid;
    __nv_bfloat16 *pWtHi, *pWtLo;
    cudaGetSymbolAddress((void**)&pXWr, g_XWr);
    cudaGetSymbolAddress((void**)&pP1r, g_P1r);
    cudaGetSymbolAddress((void**)&pXWc, g_XWc);
    cudaGetSymbolAddress((void**)&pP1c, g_P1c);
    cudaGetSymbolAddress((void**)&pDr, g_dinv_r);
    cudaGetSymbolAddress((void**)&pDc, g_dinv_c);
    cudaGetSymbolAddress((void**)&pWfr, g_Wf_r);
    cudaGetSymbolAddress((void**)&pWfc, g_Wf_c);
    cudaGetSymbolAddress((void**)&pWtHi, g_WfT_hi);
    cudaGetSymbolAddress((void**)&pWtLo, g_WfT_lo);
    cudaGetSymbolAddress((void**)&pPoolR, g_pooled_r);
    cudaGetSymbolAddress((void**)&pPoolG, g_pooledG);
    cudaGetSymbolAddress((void**)&pGraphs, g_graphs);
    cudaGetSymbolAddress((void**)&pPoolC, g_poolC);
    cudaGetSymbolAddress((void**)&pReps, g_reps);
    cudaGetSymbolAddress((void**)&pHmid, g_hmid);

    const int* r_src = rei;            const int* r_dst = rei + ERn;
    const int* c_src = cei;            const int* c_dst = cei + ECn;

    // ---- degrees / dinv ----
    fillf_kernel<<<(NRn + 255) / 256, 256>>>(pDr, NRn, 1.0f);
    deg_add_kernel<<<(ERn + 255) / 256, 256>>>(r_dst, pDr, ERn);
    inv_sqrt_kernel<<<(NRn + 255) / 256, 256>>>(pDr, NRn);
    fillf_kernel<<<(NCn + 255) / 256, 256>>>(pDc, NCn, 1.0f);
    deg_add_kernel<<<(ECn + 255) / 256, 256>>>(c_dst, pDc, ECn);
    inv_sqrt_kernel<<<(NCn + 255) / 256, 256>>>(pDc, NCn);

    // ---- fused first-layer weights: Wf = W_text @ W*1   [768,256] ----
    sgemm64_kernel<<<dim3(Hd / 64, Dd / 64), 256>>>(W_text, Hd, Wr1, nullptr, pWfr, Hd, Dd, Hd, Hd, 0);
    sgemm64_kernel<<<dim3(Hd / 64, Dd / 64), 256>>>(W_text, Hd, Wc1, nullptr, pWfc, Hd, Dd, Hd, Hd, 0);

    // ---- big GEMMs on tensor cores (bf16 split, 3-product) ----
    convtrans_kernel<<<(Dd * Hd + 255) / 256, 256>>>(pWfr, pWtHi, pWtLo);
    gemm_tc_kernel<<<dim3(2, (NRn + 127) / 128), 256>>>(repost_x, pWtHi, pWtLo, pXWr, NRn);
    convtrans_kernel<<<(Dd * Hd + 255) / 256, 256>>>(pWfc, pWtHi, pWtLo);
    gemm_tc_kernel<<<dim3(2, (NCn + 127) / 128), 256>>>(comment_x, pWtHi, pWtLo, pXWc, NCn);

    // ---- repost branch ----
    prop_self_kernel<<<NRn, Hd>>>(pXWr, pP1r, pDr, 0);
    prop_edges_kernel<<<ERn, Hd>>>(pXWr, pP1r, r_src, r_dst, pDr, 0);
    prop_self_kernel<<<NRn, Hd>>>(pP1r, pXWr, pDr, 1);
    prop_edges_kernel<<<ERn, Hd>>>(pP1r, pXWr, r_src, r_dst, pDr, 1);
    cudaMemsetAsync(pPoolR, 0, (size_t)Bsz * Hd * sizeof(float));
    pool_partial_kernel<<<dim3(Bsz, 16), Hd>>>(pXWr, rbatch, NRn, pPoolR, 16);
    pool_div_kernel<<<Bsz, Hd>>>(pPoolR, rbatch, NRn, pPoolR, Hd);

    // ---- comment branch ----
    prop_self_kernel<<<NCn, Hd>>>(pXWc, pP1c, pDc, 0);
    prop_edges_kernel<<<ECn, Hd>>>(pXWc, pP1c, c_src, c_dst, pDc, 0);
    prop_self_kernel<<<NCn, Hd>>>(pP1c, pXWc, pDc, 1);
    prop_edges_kernel<<<ECn, Hd>>>(pP1c, pXWc, c_src, c_dst, pDc, 1);
    cudaMemsetAsync(pPoolG, 0, (size_t)Gn * Hd * sizeof(float));
    pool_partial_kernel<<<dim3(Gn, 4), Hd>>>(pXWc, cbatch, NCn, pPoolG, 4);
    pool_div_kernel<<<Gn, Hd>>>(pPoolG, cbatch, NCn, pPoolG, Hd);

    sgemm64_kernel<<<dim3(Hd / 64, Gn / 64), 256>>>(pPoolG, Hd, Wc2, nullptr, pGraphs, Hd, Gn, Hd, Hd, 0);
    cudaMemsetAsync(pPoolC, 0, (size_t)Bsz * Hd * sizeof(float));
    pool_partial_kernel<<<dim3(Bsz, 2), Hd>>>(pGraphs, cgb, Gn, pPoolC, 2);
    pool_div_kernel<<<Bsz, Hd>>>(pPoolC, cgb, Gn, pReps + 2 * Hd, 5 * Hd);

    // ---- assemble reps [64, 1280] ----
    sgemm64_kernel<<<dim3(Hd / 64, 1), 256>>>(content, Dd, W_text, nullptr, pReps + 0 * Hd, 5 * Hd, Bsz, Hd, Dd, 0);
    sgemm64_kernel<<<dim3(Hd / 64, 1), 256>>>(pPoolR, Hd, Wr2, nullptr, pReps + 1 * Hd, 5 * Hd, Bsz, Hd, Hd, 0);
    sgemm64_kernel<<<dim3(Hd / 64, 1), 256>>>(video, Dd, W_video, nullptr, pReps + 3 * Hd, 5 * Hd, Bsz, Hd, Dd, 0);
    sgemm64_kernel<<<dim3(Hd / 64, 1), 256>>>(image, Dd, W_image, nullptr, pReps + 4 * Hd, 5 * Hd, Bsz, Hd, Dd, 0);

    // ---- MLP head ----
    sgemm64_kernel<<<dim3(Hd / 64, 1), 256>>>(pReps, 5 * Hd, W1, b1, pHmid, Hd, Bsz, Hd, 5 * Hd, 1);
    head_kernel<<<1, 128>>>(pHmid, W2, b2, label, out, out_size);
}

// round 3
// speedup vs baseline: 1.7784x; 1.2693x over previous
#include <cuda_runtime.h>
#include <cuda_bf16.h>
#include <math.h>
#include <stdint.h>

// ---------------- problem constants ----------------
#define Bsz 64
#define Hd  256
#define Dd  768
#define NRn 100000
#define ERn 400000
#define NCn 100000
#define ECn 300000
#define Gn  512

// ---------------- device scratch ----------------
__device__ float g_XWr[(size_t)NRn * Hd];
__device__ float g_P1r[(size_t)NRn * Hd];
__device__ float g_XWc[(size_t)NCn * Hd];
__device__ float g_P1c[(size_t)NCn * Hd];
__device__ float g_dinv_r[NRn];
__device__ float g_dinv_c[NCn];
__device__ float g_Wf_r[Dd * Hd];
__device__ float g_Wf_c[Dd * Hd];
__device__ __nv_bfloat16 g_WfT_hi[Hd * Dd];
__device__ __nv_bfloat16 g_WfT_lo[Hd * Dd];
__device__ float g_pooled_r[Bsz * Hd];
__device__ float g_pooledG[Gn * Hd];
__device__ float g_graphs[Gn * Hd];
__device__ float g_reps[Bsz * 5 * Hd];
__device__ float g_hmid[Bsz * Hd];
// CSR scratch
__device__ int g_cnt_r[NRn];
__device__ int g_cnt_c[NCn];
__device__ int g_rowoff_r[NRn + 1];
__device__ int g_rowoff_c[NCn + 1];
__device__ int g_esrc_r[ERn];
__device__ int g_esrc_c[ECn];

// ---------------- small utility kernels ----------------
__global__ void filli_kernel(int* p, int n, int v) {
    int i = blockIdx.x * blockDim.x + threadIdx.x;
    if (i < n) p[i] = v;
}

__global__ void count_kernel(const int* __restrict__ dst, int* __restrict__ cnt, int E) {
    int e = blockIdx.x * blockDim.x + threadIdx.x;
    if (e < E) atomicAdd(&cnt[dst[e]], 1);
}

__global__ void dinv_kernel(const int* __restrict__ cnt, float* __restrict__ dinv, int n) {
    int i = blockIdx.x * blockDim.x + threadIdx.x;
    if (i < n) dinv[i] = rsqrtf((float)(cnt[i] + 1));
}

// single-block exclusive scan of cnt[0..n) -> rowoff[0..n]
__global__ void scan_kernel(const int* __restrict__ cnt, int* __restrict__ rowoff, int n) {
    __shared__ int partial[1024];
    int tid = threadIdx.x;
    int chunk = (n + 1023) / 1024;
    int s0 = tid * chunk;
    int s1 = s0 + chunk; if (s1 > n) s1 = n;
    int sum = 0;
    for (int i = s0; i < s1; i++) sum += cnt[i];
    partial[tid] = sum;
    __syncthreads();
    for (int off = 1; off < 1024; off <<= 1) {
        int v = (tid >= off) ? partial[tid - off] : 0;
        __syncthreads();
        partial[tid] += v;
        __syncthreads();
    }
    int run = (tid > 0) ? partial[tid - 1] : 0;
    for (int i = s0; i < s1; i++) { rowoff[i] = run; run += cnt[i]; }
    if (tid == 1023) rowoff[n] = partial[1023];
}

// scatter edges into CSR slots (cursor = cnt array re-zeroed)
__global__ void scatter_kernel(const int* __restrict__ src, const int* __restrict__ dst,
                               const int* __restrict__ rowoff, int* __restrict__ cursor,
                               int* __restrict__ esrc, int E) {
    int e = blockIdx.x * blockDim.x + threadIdx.x;
    if (e < E) {
        int d = dst[e];
        int pos = rowoff[d] + atomicAdd(&cursor[d], 1);
        esrc[pos] = src[e];
    }
}

// ---------------- CSR gather propagation ----------------
// out[n] = dinv[n] * ( in[n]*dinv[n] + sum_{s in nbr(n)} act(in[s])*dinv[s] )
__global__ __launch_bounds__(256) void gather_prop_kernel(
    const float* __restrict__ in, float* __restrict__ out,
    const int* __restrict__ rowoff, const int* __restrict__ esrc,
    const float* __restrict__ dinv, int doRelu)
{
    int n = blockIdx.x;
    int j = threadIdx.x;
    int beg = rowoff[n], end = rowoff[n + 1];
    float di = dinv[n];
    float v = in[(size_t)n * Hd + j];
    if (doRelu) v = fmaxf(v, 0.0f);
    float acc = v * di;
    int e = beg;
    for (; e + 2 <= end; e += 2) {
        int s0 = __ldg(&esrc[e]);
        int s1 = __ldg(&esrc[e + 1]);
        float w0 = __ldg(&dinv[s0]);
        float w1 = __ldg(&dinv[s1]);
        float x0 = __ldg(&in[(size_t)s0 * Hd + j]);
        float x1 = __ldg(&in[(size_t)s1 * Hd + j]);
        if (doRelu) { x0 = fmaxf(x0, 0.0f); x1 = fmaxf(x1, 0.0f); }
        acc += x0 * w0 + x1 * w1;
    }
    if (e < end) {
        int s0 = __ldg(&esrc[e]);
        float w0 = __ldg(&dinv[s0]);
        float x0 = __ldg(&in[(size_t)s0 * Hd + j]);
        if (doRelu) x0 = fmaxf(x0, 0.0f);
        acc += x0 * w0;
    }
    out[(size_t)n * Hd + j] = acc * di;
}

// layer-2 gather fused with segment-sum pooling: pool[batch[n]] += row
__global__ __launch_bounds__(256) void gather_prop_pool_kernel(
    const float* __restrict__ in,
    const int* __restrict__ rowoff, const int* __restrict__ esrc,
    const float* __restrict__ dinv, const int* __restrict__ batch,
    float* __restrict__ pool)
{
    int n = blockIdx.x;
    int j = threadIdx.x;
    int beg = rowoff[n], end = rowoff[n + 1];
    float di = dinv[n];
    float v = fmaxf(in[(size_t)n * Hd + j], 0.0f);
    float acc = v * di;
    int e = beg;
    for (; e + 2 <= end; e += 2) {
        int s0 = __ldg(&esrc[e]);
        int s1 = __ldg(&esrc[e + 1]);
        float w0 = __ldg(&dinv[s0]);
        float w1 = __ldg(&dinv[s1]);
        float x0 = fmaxf(__ldg(&in[(size_t)s0 * Hd + j]), 0.0f);
        float x1 = fmaxf(__ldg(&in[(size_t)s1 * Hd + j]), 0.0f);
        acc += x0 * w0 + x1 * w1;
    }
    if (e < end) {
        int s0 = __ldg(&esrc[e]);
        float w0 = __ldg(&dinv[s0]);
        float x0 = fmaxf(__ldg(&in[(size_t)s0 * Hd + j]), 0.0f);
        acc += x0 * w0;
    }
    int b = __ldg(&batch[n]);
    atomicAdd(&pool[(size_t)b * Hd + j], acc * di);
}

__device__ __forceinline__ int lower_bound_dev(const int* a, int n, int v) {
    int lo = 0, hi = n;
    while (lo < hi) { int mid = (lo + hi) >> 1; if (a[mid] < v) lo = mid + 1; else hi = mid; }
    return lo;
}

__global__ void pool_partial_kernel(const float* __restrict__ x, const int* __restrict__ seg,
                                    int n, float* __restrict__ acc, int chunks) {
    int b = blockIdx.x;
    int chunk = blockIdx.y;
    int start = lower_bound_dev(seg, n, b);
    int end   = lower_bound_dev(seg, n, b + 1);
    int len = end - start;
    if (len <= 0) return;
    int per = (len + chunks - 1) / chunks;
    int s0 = start + chunk * per;
    int s1 = s0 + per; if (s1 > end) s1 = end;
    if (s0 >= s1) return;
    int j = threadIdx.x;
    float a = 0.0f;
    for (int r = s0; r < s1; r++) a += x[(size_t)r * Hd + j];
    atomicAdd(&acc[b * Hd + j], a);
}

__global__ void pool_div_kernel(const float* __restrict__ acc, const int* __restrict__ seg,
                                int n, float* __restrict__ dst, int ld) {
    int b = blockIdx.x;
    int j = threadIdx.x;
    int cnt = lower_bound_dev(seg, n, b + 1) - lower_bound_dev(seg, n, b);
    float c = fmaxf((float)cnt, 1.0f);
    dst[(size_t)b * ld + j] = acc[b * Hd + j] / c;
}

// ---------------- transpose + bf16 split of fused weight ----------------
__global__ void convtrans_kernel(const float* __restrict__ W,
                                 __nv_bfloat16* __restrict__ oHi,
                                 __nv_bfloat16* __restrict__ oLo) {
    int i = blockIdx.x * blockDim.x + threadIdx.x;
    if (i >= Dd * Hd) return;
    int k = i / Hd, n = i % Hd;
    float f = W[i];
    __nv_bfloat16 h = __float2bfloat16(f);
    float r = f - __bfloat162float(h);
    oHi[(size_t)n * Dd + k] = h;
    oLo[(size_t)n * Dd + k] = __float2bfloat16(r);
}

// ---------------- tensor-core GEMM (bf16 split, 3 products) ----------------
__device__ __forceinline__ void ldsm_x4(uint32_t r[4], const void* p) {
    uint32_t a = (uint32_t)__cvta_generic_to_shared(p);
    asm volatile("ldmatrix.sync.aligned.m8n8.x4.shared.b16 {%0,%1,%2,%3}, [%4];"
                 : "=r"(r[0]), "=r"(r[1]), "=r"(r[2]), "=r"(r[3]) : "r"(a));
}

__device__ __forceinline__ void mma_bf16(float acc[4], uint32_t a0, uint32_t a1,
                                         uint32_t a2, uint32_t a3,
                                         uint32_t b0, uint32_t b1) {
    asm volatile(
        "mma.sync.aligned.m16n8k16.row.col.f32.bf16.bf16.f32 "
        "{%0,%1,%2,%3},{%4,%5,%6,%7},{%8,%9},{%0,%1,%2,%3};"
        : "+f"(acc[0]), "+f"(acc[1]), "+f"(acc[2]), "+f"(acc[3])
        : "r"(a0), "r"(a1), "r"(a2), "r"(a3), "r"(b0), "r"(b1));
}

__global__ __launch_bounds__(256) void gemm_tc_kernel(
    const float* __restrict__ A,
    const __nv_bfloat16* __restrict__ BtHi,
    const __nv_bfloat16* __restrict__ BtLo,
    float* __restrict__ C, int M)
{
    const int K = Dd;
    const int LDS_STRIDE = 40;
    __shared__ __nv_bfloat16 AsH[128][LDS_STRIDE];
    __shared__ __nv_bfloat16 AsL[128][LDS_STRIDE];
    __shared__ __nv_bfloat16 BsH[128][LDS_STRIDE];
    __shared__ __nv_bfloat16 BsL[128][LDS_STRIDE];

    int tid = threadIdx.x;
    int warp = tid >> 5, lane = tid & 31;
    int bRow = blockIdx.y * 128, bCol = blockIdx.x * 128;
    int wm = (warp >> 2) * 64;
    int wn = (warp & 3) * 32;

    float acc[4][4][4];
#pragma unroll
    for (int a = 0; a < 4; a++)
#pragma unroll
        for (int b = 0; b < 4; b++)
#pragma unroll
            for (int c = 0; c < 4; c++) acc[a][b][c] = 0.0f;

    float4 aR[4];
    const float4 z4 = make_float4(0.f, 0.f, 0.f, 0.f);
#define LOAD_A(k0)                                                            \
    {                                                                         \
        _Pragma("unroll")                                                     \
        for (int l = 0; l < 4; l++) {                                         \
            int i = tid + l * 256;                                            \
            int r = i >> 3, c4 = (i & 7) * 4;                                 \
            int gr = bRow + r;                                                \
            aR[l] = (gr < M) ? *(const float4*)&A[(size_t)gr * K + (k0) + c4] \
                             : z4;                                            \
        }                                                                     \
    }

    LOAD_A(0);

    for (int it = 0; it < K / 32; it++) {
        int k0 = it * 32;
#pragma unroll
        for (int l = 0; l < 2; l++) {
            int i = tid + l * 256;
            int r = i >> 2, c8 = (i & 3) * 8;
            *(float4*)&BsH[r][c8] = *(const float4*)&BtHi[(size_t)(bCol + r) * K + k0 + c8];
            *(float4*)&BsL[r][c8] = *(const float4*)&BtLo[(size_t)(bCol + r) * K + k0 + c8];
        }
#pragma unroll
        for (int l = 0; l < 4; l++) {
            int i = tid + l * 256;
            int r = i >> 3, c4 = (i & 7) * 4;
            float f[4] = {aR[l].x, aR[l].y, aR[l].z, aR[l].w};
            __nv_bfloat16 h[4], lo[4];
#pragma unroll
            for (int j = 0; j < 4; j++) {
                h[j] = __float2bfloat16(f[j]);
                lo[j] = __float2bfloat16(f[j] - __bfloat162float(h[j]));
            }
            *(__nv_bfloat162*)&AsH[r][c4]     = __nv_bfloat162(h[0], h[1]);
            *(__nv_bfloat162*)&AsH[r][c4 + 2] = __nv_bfloat162(h[2], h[3]);
            *(__nv_bfloat162*)&AsL[r][c4]     = __nv_bfloat162(lo[0], lo[1]);
            *(__nv_bfloat162*)&AsL[r][c4 + 2] = __nv_bfloat162(lo[2], lo[3]);
        }
        __syncthreads();

        if (it < K / 32 - 1) LOAD_A(k0 + 32);

        int mt = lane >> 3, ri = lane & 7;
#pragma unroll
        for (int ks = 0; ks < 2; ks++) {
            int colOff = ks * 16 + (mt >> 1) * 8;
            uint32_t aH[4][4], aL[4][4], bH[2][4], bL[2][4];
#pragma unroll
            for (int mi = 0; mi < 4; mi++) {
                int row = wm + mi * 16 + (mt & 1) * 8 + ri;
                ldsm_x4(aH[mi], &AsH[row][colOff]);
                ldsm_x4(aL[mi], &AsL[row][colOff]);
            }
#pragma unroll
            for (int bj = 0; bj < 2; bj++) {
                int row = wn + bj * 16 + (mt & 1) * 8 + ri;
                ldsm_x4(bH[bj], &BsH[row][colOff]);
                ldsm_x4(bL[bj], &BsL[row][colOff]);
            }
#pragma unroll
            for (int mi = 0; mi < 4; mi++)
#pragma unroll
                for (int nj = 0; nj < 4; nj++) {
                    int bj = nj >> 1, s = nj & 1;
                    mma_bf16(acc[mi][nj], aH[mi][0], aH[mi][1], aH[mi][2], aH[mi][3],
                             bH[bj][s], bH[bj][s + 2]);
                    mma_bf16(acc[mi][nj], aH[mi][0], aH[mi][1], aH[mi][2], aH[mi][3],
                             bL[bj][s], bL[bj][s + 2]);
                    mma_bf16(acc[mi][nj], aL[mi][0], aL[mi][1], aL[mi][2], aL[mi][3],
                             bH[bj][s], bH[bj][s + 2]);
                }
        }
        __syncthreads();
    }

    int g = lane >> 2, t = lane & 3;
#pragma unroll
    for (int mi = 0; mi < 4; mi++)
#pragma unroll
        for (int nj = 0; nj < 4; nj++) {
            int row = bRow + wm + mi * 16 + g;
            int col = bCol + wn + nj * 8 + t * 2;
            if (row < M)
                *(float2*)&C[(size_t)row * Hd + col] = make_float2(acc[mi][nj][0], acc[mi][nj][1]);
            if (row + 8 < M)
                *(float2*)&C[(size_t)(row + 8) * Hd + col] = make_float2(acc[mi][nj][2], acc[mi][nj][3]);
        }
#undef LOAD_A
}

// ---------------- small fp32 GEMM ----------------
__global__ __launch_bounds__(256) void sgemm64_kernel(const float* __restrict__ A, int lda,
                                                      const float* __restrict__ Bm,
                                                      const float* __restrict__ bias,
                                                      float* __restrict__ C, int ldc,
                                                      int M, int N, int K, int doRelu) {
    const int BM = 64, BN = 64, BK = 16, TM = 4, TN = 4;
    __shared__ float As[BK][BM];
    __shared__ float Bs[BK][BN];
    const int tid = threadIdx.x;
    const int bRow = blockIdx.y * BM;
    const int bCol = blockIdx.x * BN;
    const int tx = tid % 16;
    const int ty = tid / 16;

    float acc[TM][TN];
#pragma unroll
    for (int i = 0; i < TM; i++)
#pragma unroll
        for (int j = 0; j < TN; j++) acc[i][j] = 0.0f;

    for (int k0 = 0; k0 < K; k0 += BK) {
        {
            int i = tid;
            int r = i >> 2;
            int c4 = (i & 3) << 2;
            int grow = bRow + r;
            float4 v = make_float4(0.f, 0.f, 0.f, 0.f);
            if (grow < M) v = *reinterpret_cast<const float4*>(&A[(size_t)grow * lda + k0 + c4]);
            As[c4 + 0][r] = v.x; As[c4 + 1][r] = v.y; As[c4 + 2][r] = v.z; As[c4 + 3][r] = v.w;
        }
        {
            int i = tid;
            int r = i >> 4;
            int c = (i & 15) << 2;
            float4 v = *reinterpret_cast<const float4*>(&Bm[(size_t)(k0 + r) * N + bCol + c]);
            *reinterpret_cast<float4*>(&Bs[r][c]) = v;
        }
        __syncthreads();

        float ar[TM], br[TN];
#pragma unroll
        for (int kk = 0; kk < BK; kk++) {
#pragma unroll
            for (int i = 0; i < TM; i++) ar[i] = As[kk][ty * TM + i];
#pragma unroll
            for (int j = 0; j < TN; j++) br[j] = Bs[kk][tx * TN + j];
#pragma unroll
            for (int i = 0; i < TM; i++)
#pragma unroll
                for (int j = 0; j < TN; j++) acc[i][j] += ar[i] * br[j];
        }
        __syncthreads();
    }

#pragma unroll
    for (int i = 0; i < TM; i++) {
        int grow = bRow + ty * TM + i;
        if (grow >= M) continue;
#pragma unroll
        for (int j = 0; j < TN; j++) {
            int gcol = bCol + tx * TN + j;
            float v = acc[i][j];
            if (bias) v += bias[gcol];
            if (doRelu) v = fmaxf(v, 0.0f);
            C[(size_t)grow * ldc + gcol] = v;
        }
    }
}

// ---------------- head ----------------
__global__ void head_kernel(const float* __restrict__ h, const float* __restrict__ W2,
                            const float* __restrict__ b2, const int* __restrict__ label,
                            float* __restrict__ out, int out_size) {
    __shared__ float preds[Bsz][2];
    int tid = threadIdx.x;
    if (tid < Bsz * 2) {
        int r = tid >> 1, c = tid & 1;
        float s = b2[c];
        for (int k = 0; k < Hd; k++) s += h[r * Hd + k] * W2[k * 2 + c];
        preds[r][c] = s;
    }
    __syncthreads();
    if (tid < Bsz * 2 && tid < out_size) out[tid] = preds[tid >> 1][tid & 1];
    if (tid == 0 && out_size >= Bsz * 2 + 1) {
        float loss = 0.0f;
        for (int r = 0; r < Bsz; r++) {
            float a = preds[r][0], b = preds[r][1];
            float m = fmaxf(a, b);
            float lse = m + logf(expf(a - m) + expf(b - m));
            int y = label[r];
            loss += lse - (y ? b : a);
        }
        out[Bsz * 2] = loss / (float)Bsz;
    }
}

// ---------------- launch ----------------
extern "C" void kernel_launch(void* const* d_in, const int* in_sizes, int n_in,
                              void* d_out, int out_size) {
    const float* content  = (const float*)d_in[0];
    const float* video    = (const float*)d_in[1];
    const float* image    = (const float*)d_in[2];
    const float* repost_x = (const float*)d_in[3];
    const float* comment_x= (const float*)d_in[4];
    const float* W_text   = (const float*)d_in[5];
    const float* W_video  = (const float*)d_in[6];
    const float* W_image  = (const float*)d_in[7];
    const float* Wr1      = (const float*)d_in[8];
    const float* Wr2      = (const float*)d_in[9];
    const float* Wc1      = (const float*)d_in[10];
    const float* Wc2      = (const float*)d_in[11];
    const float* W1       = (const float*)d_in[12];
    const float* b1       = (const float*)d_in[13];
    const float* W2       = (const float*)d_in[14];
    const float* b2       = (const float*)d_in[15];
    const int* rei        = (const int*)d_in[16];
    const int* rbatch     = (const int*)d_in[17];
    const int* cei        = (const int*)d_in[18];
    const int* cbatch     = (const int*)d_in[19];
    const int* cgb        = (const int*)d_in[20];
    const int* label      = (const int*)d_in[21];
    float* out            = (float*)d_out;

    float *pXWr, *pP1r, *pXWc, *pP1c, *pDr, *pDc, *pWfr, *pWfc;
    float *pPoolR, *pPoolG, *pGraphs, *pReps, *pHmid;
    __nv_bfloat16 *pWtHi, *pWtLo;
    int *pCntR, *pCntC, *pRoR, *pRoC, *pEsR, *pEsC;
    cudaGetSymbolAddress((void**)&pXWr, g_XWr);
    cudaGetSymbolAddress((void**)&pP1r, g_P1r);
    cudaGetSymbolAddress((void**)&pXWc, g_XWc);
    cudaGetSymbolAddress((void**)&pP1c, g_P1c);
    cudaGetSymbolAddress((void**)&pDr, g_dinv_r);
    cudaGetSymbolAddress((void**)&pDc, g_dinv_c);
    cudaGetSymbolAddress((void**)&pWfr, g_Wf_r);
    cudaGetSymbolAddress((void**)&pWfc, g_Wf_c);
    cudaGetSymbolAddress((void**)&pWtHi, g_WfT_hi);
    cudaGetSymbolAddress((void**)&pWtLo, g_WfT_lo);
    cudaGetSymbolAddress((void**)&pPoolR, g_pooled_r);
    cudaGetSymbolAddress((void**)&pPoolG, g_pooledG);
    cudaGetSymbolAddress((void**)&pGraphs, g_graphs);
    cudaGetSymbolAddress((void**)&pReps, g_reps);
    cudaGetSymbolAddress((void**)&pHmid, g_hmid);
    cudaGetSymbolAddress((void**)&pCntR, g_cnt_r);
    cudaGetSymbolAddress((void**)&pCntC, g_cnt_c);
    cudaGetSymbolAddress((void**)&pRoR, g_rowoff_r);
    cudaGetSymbolAddress((void**)&pRoC, g_rowoff_c);
    cudaGetSymbolAddress((void**)&pEsR, g_esrc_r);
    cudaGetSymbolAddress((void**)&pEsC, g_esrc_c);

    const int* r_src = rei;            const int* r_dst = rei + ERn;
    const int* c_src = cei;            const int* c_dst = cei + ECn;

    // ---- CSR build: repost ----
    filli_kernel<<<(NRn + 255) / 256, 256>>>(pCntR, NRn, 0);
    count_kernel<<<(ERn + 255) / 256, 256>>>(r_dst, pCntR, ERn);
    dinv_kernel<<<(NRn + 255) / 256, 256>>>(pCntR, pDr, NRn);
    scan_kernel<<<1, 1024>>>(pCntR, pRoR, NRn);
    filli_kernel<<<(NRn + 255) / 256, 256>>>(pCntR, NRn, 0);
    scatter_kernel<<<(ERn + 255) / 256, 256>>>(r_src, r_dst, pRoR, pCntR, pEsR, ERn);

    // ---- CSR build: comment ----
    filli_kernel<<<(NCn + 255) / 256, 256>>>(pCntC, NCn, 0);
    count_kernel<<<(ECn + 255) / 256, 256>>>(c_dst, pCntC, ECn);
    dinv_kernel<<<(NCn + 255) / 256, 256>>>(pCntC, pDc, NCn);
    scan_kernel<<<1, 1024>>>(pCntC, pRoC, NCn);
    filli_kernel<<<(NCn + 255) / 256, 256>>>(pCntC, NCn, 0);
    scatter_kernel<<<(ECn + 255) / 256, 256>>>(c_src, c_dst, pRoC, pCntC, pEsC, ECn);

    // ---- fused first-layer weights: Wf = W_text @ W*1   [768,256] ----
    sgemm64_kernel<<<dim3(Hd / 64, Dd / 64), 256>>>(W_text, Hd, Wr1, nullptr, pWfr, Hd, Dd, Hd, Hd, 0);
    sgemm64_kernel<<<dim3(Hd / 64, Dd / 64), 256>>>(W_text, Hd, Wc1, nullptr, pWfc, Hd, Dd, Hd, Hd, 0);

    // ---- big GEMMs on tensor cores ----
    convtrans_kernel<<<(Dd * Hd + 255) / 256, 256>>>(pWfr, pWtHi, pWtLo);
    gemm_tc_kernel<<<dim3(2, (NRn + 127) / 128), 256>>>(repost_x, pWtHi, pWtLo, pXWr, NRn);
    convtrans_kernel<<<(Dd * Hd + 255) / 256, 256>>>(pWfc, pWtHi, pWtLo);
    gemm_tc_kernel<<<dim3(2, (NCn + 127) / 128), 256>>>(comment_x, pWtHi, pWtLo, pXWc, NCn);

    // ---- repost branch: gather prop x2, layer-2 fused with pooling ----
    gather_prop_kernel<<<NRn, Hd>>>(pXWr, pP1r, pRoR, pEsR, pDr, 0);
    cudaMemsetAsync(pPoolR, 0, (size_t)Bsz * Hd * sizeof(float));
    gather_prop_pool_kernel<<<NRn, Hd>>>(pP1r, pRoR, pEsR, pDr, rbatch, pPoolR);
    pool_div_kernel<<<Bsz, Hd>>>(pPoolR, rbatch, NRn, pPoolR, Hd);

    // ---- comment branch ----
    gather_prop_kernel<<<NCn, Hd>>>(pXWc, pP1c, pRoC, pEsC, pDc, 0);
    cudaMemsetAsync(pPoolG, 0, (size_t)Gn * Hd * sizeof(float));
    gather_prop_pool_kernel<<<NCn, Hd>>>(pP1c, pRoC, pEsC, pDc, cbatch, pPoolG);
    pool_div_kernel<<<Gn, Hd>>>(pPoolG, cbatch, NCn, pPoolG, Hd);

    sgemm64_kernel<<<dim3(Hd / 64, Gn / 64), 256>>>(pPoolG, Hd, Wc2, nullptr, pGraphs, Hd, Gn, Hd, Hd, 0);
    cudaMemsetAsync(pReps + 2 * Hd, 0, sizeof(float));  // no-op keeper (strided dst written below)
    {
        // second-level pool: graphs -> reps[:, 2H:3H]
        static_assert(Gn % 2 == 0, "");
    }
    cudaMemsetAsync(pHmid, 0, (size_t)Bsz * Hd * sizeof(float));  // reuse as temp acc for poolC
    pool_partial_kernel<<<dim3(Bsz, 2), Hd>>>(pGraphs, cgb, Gn, pHmid, 2);
    pool_div_kernel<<<Bsz, Hd>>>(pHmid, cgb, Gn, pReps + 2 * Hd, 5 * Hd);

    // ---- assemble reps [64, 1280] ----
    sgemm64_kernel<<<dim3(Hd / 64, 1), 256>>>(content, Dd, W_text, nullptr, pReps + 0 * Hd, 5 * Hd, Bsz, Hd, Dd, 0);
    sgemm64_kernel<<<dim3(Hd / 64, 1), 256>>>(pPoolR, Hd, Wr2, nullptr, pReps + 1 * Hd, 5 * Hd, Bsz, Hd, Hd, 0);
    sgemm64_kernel<<<dim3(Hd / 64, 1), 256>>>(video, Dd, W_video, nullptr, pReps + 3 * Hd, 5 * Hd, Bsz, Hd, Dd, 0);
    sgemm64_kernel<<<dim3(Hd / 64, 1), 256>>>(image, Dd, W_image, nullptr, pReps + 4 * Hd, 5 * Hd, Bsz, Hd, Dd, 0);

    // ---- MLP head ----
    sgemm64_kernel<<<dim3(Hd / 64, 1), 256>>>(pReps, 5 * Hd, W1, b1, pHmid, Hd, Bsz, Hd, 5 * Hd, 1);
    head_kernel<<<1, 128>>>(pHmid, W2, b2, label, out, out_size);
}